// round 10
// baseline (speedup 1.0000x reference)
#include <cuda_runtime.h>

#define BB 16
#define NNODE 512
#define DD 12
#define HIDN 32
#define NHEAD 4
#define CDIM 8

typedef unsigned long long ull;

// ---------------- scratch (no allocs allowed) ----------------
__device__ __align__(16) float g_buf  [BB*NNODE*HIDN];
__device__ __align__(16) float as_buf [BB*NNODE*NHEAD];
__device__ __align__(16) float ad_buf [BB*NNODE*NHEAD];
__device__ __align__(16) float ti_buf [BB*NNODE*HIDN];   // ti + b1 folded, row-major [node][32]
__device__ __align__(16) float tjT_buf[BB*HIDN*NNODE];   // transposed: [(b*16+p)*512 + j] ull pairs
__device__ __align__(16) float pi_buf [BB*NNODE];        // 0.5 * sum_h w2[h]*ti'[node][h]
__device__ __align__(16) float pj_buf [BB*NNODE];        // 0.5 * sum_h w2[h]*tj [node][h]

// ---------------- f32x2 helpers (Blackwell packed fp32) ----------------
__device__ __forceinline__ ull add2(ull a, ull b){ ull r; asm("add.rn.f32x2 %0, %1, %2;" : "=l"(r) : "l"(a), "l"(b)); return r; }
__device__ __forceinline__ ull fma2(ull a, ull b, ull c){ ull r; asm("fma.rn.f32x2 %0, %1, %2, %3;" : "=l"(r) : "l"(a), "l"(b), "l"(c)); return r; }
__device__ __forceinline__ ull pack2(float x, float y){
    ull r; asm("mov.b64 %0, {%1, %2};" : "=l"(r) : "r"(__float_as_uint(x)), "r"(__float_as_uint(y))); return r;
}
__device__ __forceinline__ float2 unpack2(ull v){
    unsigned lo, hi; asm("mov.b64 {%0, %1}, %2;" : "=r"(lo), "=r"(hi) : "l"(v));
    return make_float2(__uint_as_float(lo), __uint_as_float(hi));
}
__device__ __forceinline__ float ex2f(float x){ float r; asm("ex2.approx.f32 %0, %1;" : "=f"(r) : "f"(x)); return r; }

// ================= K1: per-node embeddings h -> g, a_s, a_d =================
// 512 blocks x 128 threads; 16 nodes/block; thread = (node, k-quartet).
// Head sums combined across quartet pairs via shfl_xor(16).
__global__ void __launch_bounds__(128) k1_embed(
    const float* __restrict__ x, const float* __restrict__ Wp, const float* __restrict__ bp,
    const float* __restrict__ Wg, const float* __restrict__ att_src, const float* __restrict__ att_dst)
{
    __shared__ float xs[16*12];
    __shared__ float Wp_s[HIDN*DD];
    __shared__ float bp_s[HIDN];
    __shared__ float Wg_s[HIDN*HIDN];
    __shared__ float asr_s[HIDN], adr_s[HIDN];

    int t  = threadIdx.x;
    int nb = blockIdx.x * 16;

    for (int i = t; i < 16*12; i += 128) xs[i] = x[(size_t)nb*12 + i];
    for (int i = t; i < HIDN*DD; i += 128) Wp_s[i] = Wp[i];
    for (int i = t; i < HIDN*HIDN; i += 128) Wg_s[i] = Wg[i];
    if (t < HIDN) { bp_s[t] = bp[t]; asr_s[t] = att_src[t]; adr_s[t] = att_dst[t]; }
    __syncthreads();

    int n = t & 15, q = t >> 4;    // q = k-quartet (0..7); head = q>>1

    float xv[DD];
#pragma unroll
    for (int d = 0; d < DD; ++d) xv[d] = xs[n*DD + d];

    float hv[HIDN];
#pragma unroll
    for (int k = 0; k < HIDN; ++k) {
        float acc = bp_s[k];
#pragma unroll
        for (int d = 0; d < DD; ++d) acc = fmaf(xv[d], Wp_s[k*DD + d], acc);
        hv[k] = fmaxf(acc, 0.f);
    }

    float gv[4];
    float asum = 0.f, adsum = 0.f;
#pragma unroll
    for (int c = 0; c < 4; ++c) {
        int k = q*4 + c;
        float acc = 0.f;
#pragma unroll
        for (int d = 0; d < HIDN; ++d) acc = fmaf(hv[d], Wg_s[k*HIDN + d], acc);
        gv[c] = acc;
        asum  = fmaf(acc, asr_s[k], asum);
        adsum = fmaf(acc, adr_s[k], adsum);
    }
    int node = nb + n;
    *(float4*)(g_buf + (size_t)node*HIDN + q*4) = make_float4(gv[0], gv[1], gv[2], gv[3]);

    // combine the two quartets of each head (partner = t^16, same warp)
    asum  += __shfl_xor_sync(0xffffffffu, asum, 16);
    adsum += __shfl_xor_sync(0xffffffffu, adsum, 16);
    if (!(q & 1)) {
        as_buf[node*NHEAD + (q >> 1)] = asum;
        ad_buf[node*NHEAD + (q >> 1)] = adsum;
    }
}

// ================= K2: attention softmax + h_gnn + ti/tjT + pi/pj =================
// Grid (32 j-tiles x 16 b), 256 threads, static smem ~39.4KB (4 blocks/SM capacity).
// Warp w = private 64-i segment; covers 16 j (2 j-groups per lane).
__global__ void __launch_bounds__(256) k2_attn(
    const int* __restrict__ adj, const float* __restrict__ bias_g,
    const float* __restrict__ W1, const float* __restrict__ b1,
    const float* __restrict__ w2)
{
    __shared__ float    part_s[8*16*4*9];      // seg, j, h, (den + 8 num) = 18432B
    __shared__ float    asT_s[4*520];          // a_s transposed
    __shared__ unsigned mask_s[NNODE];         // (adj|eye) 16-bit column masks
    __shared__ float    hg_s[16*33];
    __shared__ float    w2_s[HIDN];
    __shared__ float    W1T_s[32*65];          // W1T[d][o], pad 65

    int t  = threadIdx.x;
    int b  = blockIdx.y;
    int j0 = blockIdx.x * 16;
    int w = t >> 5, lane = t & 31;

    const float* asp = as_buf + (size_t)b * NNODE * NHEAD;
    for (int idx = t; idx < NNODE*NHEAD; idx += 256) {
        int i = idx >> 2, h = idx & 3;
        asT_s[h*520 + i] = asp[idx];
    }
    if (t < HIDN) w2_s[t] = w2[t];

    for (int idx = t; idx < 32*64; idx += 256) {
        int r = idx >> 6, c = idx & 63;     // W1[r][c], coalesced
        int d = (c < 32) ? c : (c - 32);
        int o = (c < 32) ? r : (r + 32);
        W1T_s[d*65 + o] = W1[idx];
    }

    // mask: warp w builds its own i-segment [64w, 64w+64); 2 rows per ballot.
    {
        int jl = lane & 15, ip = lane >> 4;   // lanes 0-15: row i, 16-31: row i+1
        const int* ab = adj + (size_t)b * NNODE * NNODE + j0 + jl;
        int base = w * 64;
#pragma unroll
        for (int c = 0; c < 8; ++c) {
            int i = base + c*8;
            int a0 = ab[(size_t)(i+0+ip) * NNODE];
            int a1 = ab[(size_t)(i+2+ip) * NNODE];
            int a2 = ab[(size_t)(i+4+ip) * NNODE];
            int a3 = ab[(size_t)(i+6+ip) * NNODE];
            unsigned m0 = __ballot_sync(0xffffffffu, (a0 != 0) || (i+0+ip == j0 + jl));
            unsigned m1 = __ballot_sync(0xffffffffu, (a1 != 0) || (i+2+ip == j0 + jl));
            unsigned m2 = __ballot_sync(0xffffffffu, (a2 != 0) || (i+4+ip == j0 + jl));
            unsigned m3 = __ballot_sync(0xffffffffu, (a3 != 0) || (i+6+ip == j0 + jl));
            if (lane == 0) {
                mask_s[i+0] = m0 & 0xFFFFu; mask_s[i+1] = m0 >> 16;
                mask_s[i+2] = m1 & 0xFFFFu; mask_s[i+3] = m1 >> 16;
                mask_s[i+4] = m2 & 0xFFFFu; mask_s[i+5] = m2 >> 16;
                mask_s[i+6] = m3 & 0xFFFFu; mask_s[i+7] = m3 >> 16;
            }
        }
    }
    __syncthreads();

    int h = lane & 3, jslot = lane >> 2;   // jslot 0..7

    float adv[2];
#pragma unroll
    for (int g = 0; g < 2; ++g)
        adv[g] = ad_buf[((size_t)(b*NNODE) + j0 + g*8 + jslot)*NHEAD + h];
    unsigned bit0 = 1u << jslot;

    float den[2] = {0,0};
    ull num[8];
#pragma unroll
    for (int q = 0; q < 8; ++q) num[q] = 0ull;

    const ulonglong2* gq2 = (const ulonglong2*)(g_buf + (size_t)b * NNODE * HIDN);

    const float C06 = 0.8656170246f;   // 0.6 * log2(e)
    const float C04 = 0.5770780164f;   // 0.4 * log2(e)

    int ibeg = w * 64, iend = ibeg + 64;
#pragma unroll 2
    for (int i = ibeg; i < iend; ++i) {
        float asv   = asT_s[h*520 + i];
        unsigned mw = mask_s[i];
        ulonglong2 ga = gq2[i*8 + h*2];       // LDG.128, one L2 line per warp-i
        ulonglong2 gb = gq2[i*8 + h*2 + 1];
#pragma unroll
        for (int g = 0; g < 2; ++g) {
            float s = asv + adv[g];
            float arg = fmaf(C04, fabsf(s), C06*s);  // log2e * leakyrelu(s, 0.2)
            float e = ex2f(arg);
            e = (mw & (bit0 << (8*g))) ? e : 0.f;
            den[g] += e;
            ull e2 = pack2(e, e);
            num[4*g+0] = fma2(e2, ga.x, num[4*g+0]);
            num[4*g+1] = fma2(e2, ga.y, num[4*g+1]);
            num[4*g+2] = fma2(e2, gb.x, num[4*g+2]);
            num[4*g+3] = fma2(e2, gb.y, num[4*g+3]);
        }
    }
#pragma unroll
    for (int g = 0; g < 2; ++g) {
        float* pp = part_s + ((w*16 + g*8 + jslot)*4 + h)*9;
        pp[0] = den[g];
#pragma unroll
        for (int c = 0; c < 4; ++c) {
            float2 f = unpack2(num[4*g+c]); pp[1+2*c] = f.x; pp[2+2*c] = f.y;
        }
    }
    __syncthreads();

    // reduce 8 i-segments -> h_gnn[j][32] (+bias_g)
    if (t < 64) {
        int jl = t >> 2, hh = t & 3;
        float dn = 0.f, nm[8] = {0,0,0,0,0,0,0,0};
#pragma unroll
        for (int q = 0; q < 8; ++q) {
            const float* pp = part_s + ((q*16 + jl)*4 + hh)*9;
            dn += pp[0];
#pragma unroll
            for (int c = 0; c < 8; ++c) nm[c] += pp[1+c];
        }
        float inv = __fdividef(1.f, dn);    // diag always unmasked => dn > 0
#pragma unroll
        for (int c = 0; c < 8; ++c)
            hg_s[jl*33 + hh*8 + c] = fmaf(nm[c], inv, bias_g[hh*8 + c]);
    }
    __syncthreads();

    // ti' = h_gnn@W1[:,:32]^T + b1 ; tj = h_gnn@W1[:,32:]^T (transposed layout);
    // pi/pj via warp reduction (warp-uniform j & half).
    for (int k = t; k < 16*64; k += 256) {
        int j = k >> 6, o = k & 63;
        float acc = (o < 32) ? b1[o] : 0.f;
#pragma unroll
        for (int d = 0; d < 32; ++d) acc = fmaf(hg_s[j*33 + d], W1T_s[d*65 + o], acc);
        size_t node = (size_t)(b*NNODE) + j0 + j;
        if (o < 32) {
            ti_buf[node*32 + o] = acc;
        } else {
            int oo = o - 32;
            tjT_buf[(((size_t)b*16 + (oo>>1))*NNODE + j0 + j)*2 + (oo & 1)] = acc;
        }
        float v = acc * w2_s[o & 31];
        v += __shfl_xor_sync(0xffffffffu, v, 16);
        v += __shfl_xor_sync(0xffffffffu, v, 8);
        v += __shfl_xor_sync(0xffffffffu, v, 4);
        v += __shfl_xor_sync(0xffffffffu, v, 2);
        v += __shfl_xor_sync(0xffffffffu, v, 1);
        if (lane == 0) {
            if (o < 32) pi_buf[node] = 0.5f * v;
            else        pj_buf[node] = 0.5f * v;
        }
    }
}

// ================= K4: pairwise edge scorer =================
// sum_h w2*relu(ti+tj) = pi + pj + sum_h (w2/2)*|ti+tj| ; |.| = packed AND.
// Dual i-chains; one full wave at 2 blocks/SM; adj prefetched depth-4.
#define K4_IT 64
__global__ void __launch_bounds__(256, 2) k4_score(
    const int* __restrict__ adj, const float* __restrict__ w2,
    const float* __restrict__ b2, float* __restrict__ out)
{
    __shared__ ull   ti_s[K4_IT*16];
    __shared__ float pi_s[K4_IT];
    __shared__ ull   w2p_s[16];
    int t = threadIdx.x, lane = t & 31, w = t >> 5;
    int b  = blockIdx.z;
    int i0 = blockIdx.y * K4_IT;
    int j  = blockIdx.x * 256 + w*32 + lane;

    const ull* tiu = (const ull*)ti_buf + ((size_t)(b*NNODE) + i0)*16;
    for (int idx = t; idx < K4_IT*16; idx += 256) ti_s[idx] = tiu[idx];
    if (t < K4_IT) pi_s[t] = pi_buf[(size_t)(b*NNODE) + i0 + t];
    if (t < 16)    w2p_s[t] = pack2(0.5f*w2[2*t], 0.5f*w2[2*t+1]);
    __syncthreads();

    ull tj2[16], w2r[16];
    const ull* tjp = (const ull*)tjT_buf;
#pragma unroll
    for (int p = 0; p < 16; ++p) tj2[p] = tjp[((size_t)b*16 + p)*NNODE + j];
#pragma unroll
    for (int p = 0; p < 16; ++p) w2r[p] = w2p_s[p];
    float pj  = pj_buf[(size_t)(b*NNODE) + j];
    float b2v = b2[0] + pj;

    const int* arow = adj + ((size_t)(b*NNODE) + i0)*NNODE + j;
    float*     orow = out + ((size_t)(b*NNODE) + i0)*NNODE + j;
    const ull ABS2 = 0x7FFFFFFF7FFFFFFFull;

    for (int ib = 0; ib < K4_IT; ib += 4) {
        int av[4];
#pragma unroll
        for (int k = 0; k < 4; ++k) av[k] = arow[(size_t)(ib + k) * NNODE];

#pragma unroll
        for (int kk = 0; kk < 2; ++kk) {
            int iA = ib + kk*2, iB = iA + 1;
            const ulonglong2* tpA = (const ulonglong2*)&ti_s[iA*16];
            const ulonglong2* tpB = (const ulonglong2*)&ti_s[iB*16];
            ull aA0 = 0, aA1 = 0, aB0 = 0, aB1 = 0;
#pragma unroll
            for (int q = 0; q < 8; ++q) {
                ulonglong2 tvA = tpA[q];                  // LDS.128 broadcast (chain A)
                ulonglong2 tvB = tpB[q];                  // LDS.128 broadcast (chain B)
                ull sA0 = add2(tj2[2*q],   tvA.x) & ABS2; // packed |ti+tj|
                ull sB0 = add2(tj2[2*q],   tvB.x) & ABS2;
                ull sA1 = add2(tj2[2*q+1], tvA.y) & ABS2;
                ull sB1 = add2(tj2[2*q+1], tvB.y) & ABS2;
                aA0 = fma2(w2r[2*q],   sA0, aA0);
                aB0 = fma2(w2r[2*q],   sB0, aB0);
                aA1 = fma2(w2r[2*q+1], sA1, aA1);
                aB1 = fma2(w2r[2*q+1], sB1, aB1);
            }
            float2 sfA = unpack2(add2(aA0, aA1));
            float2 sfB = unpack2(add2(aB0, aB1));
            float logitA = sfA.x + sfA.y + pi_s[iA] + b2v;
            float logitB = sfB.x + sfB.y + pi_s[iB] + b2v;
            float eA  = ex2f(-1.4426950409f * logitA);    // exp(-logit)
            float eB  = ex2f(-1.4426950409f * logitB);
            float scA = __fdividef(1.f, 1.f + eA);
            float scB = __fdividef(1.f, 1.f + eB);

            orow[(size_t)iA * NNODE] = (av[kk*2]   != 0 && (i0 + iA) != j) ? scA : 0.f;
            orow[(size_t)iB * NNODE] = (av[kk*2+1] != 0 && (i0 + iB) != j) ? scB : 0.f;
        }
    }
}

// ================= launch =================
extern "C" void kernel_launch(void* const* d_in, const int* in_sizes, int n_in,
                              void* d_out, int out_size)
{
    const float* x        = (const float*)d_in[0];
    const int*   adj      = (const int*)  d_in[1];
    const float* Wp       = (const float*)d_in[2];
    const float* bp       = (const float*)d_in[3];
    const float* Wg       = (const float*)d_in[4];
    const float* att_src  = (const float*)d_in[5];
    const float* att_dst  = (const float*)d_in[6];
    const float* bias_g   = (const float*)d_in[7];
    const float* W1       = (const float*)d_in[8];
    const float* b1       = (const float*)d_in[9];
    const float* w2       = (const float*)d_in[10];
    const float* b2       = (const float*)d_in[11];
    float* out = (float*)d_out;

    k1_embed<<<BB*NNODE/16, 128>>>(x, Wp, bp, Wg, att_src, att_dst);

    k2_attn<<<dim3(NNODE/16, BB), 256>>>(adj, bias_g, W1, b1, w2);

    k4_score<<<dim3(2, NNODE/K4_IT, BB), 256>>>(adj, w2, b2, out);
}

// round 11
// speedup vs baseline: 1.0316x; 1.0316x over previous
#include <cuda_runtime.h>

#define BB 16
#define NNODE 512
#define DD 12
#define HIDN 32
#define NHEAD 4
#define CDIM 8

typedef unsigned long long ull;

// ---------------- scratch (no allocs allowed) ----------------
__device__ __align__(16) float g_buf  [BB*NNODE*HIDN];
__device__ __align__(16) float as_buf [BB*NNODE*NHEAD];
__device__ __align__(16) float ad_buf [BB*NNODE*NHEAD];
__device__ __align__(16) float ti_buf [BB*NNODE*HIDN];   // ti + b1 folded, row-major [node][32]
__device__ __align__(16) float tjT_buf[BB*HIDN*NNODE];   // transposed: [(b*16+p)*512 + j] ull pairs
__device__ __align__(16) float pi_buf [BB*NNODE];        // 0.5 * sum_h w2[h]*ti'[node][h]
__device__ __align__(16) float pj_buf [BB*NNODE];        // 0.5 * sum_h w2[h]*tj [node][h]

// ---------------- f32x2 helpers (Blackwell packed fp32) ----------------
__device__ __forceinline__ ull add2(ull a, ull b){ ull r; asm("add.rn.f32x2 %0, %1, %2;" : "=l"(r) : "l"(a), "l"(b)); return r; }
__device__ __forceinline__ ull fma2(ull a, ull b, ull c){ ull r; asm("fma.rn.f32x2 %0, %1, %2, %3;" : "=l"(r) : "l"(a), "l"(b), "l"(c)); return r; }
__device__ __forceinline__ ull pack2(float x, float y){
    ull r; asm("mov.b64 %0, {%1, %2};" : "=l"(r) : "r"(__float_as_uint(x)), "r"(__float_as_uint(y))); return r;
}
__device__ __forceinline__ float2 unpack2(ull v){
    unsigned lo, hi; asm("mov.b64 {%0, %1}, %2;" : "=r"(lo), "=r"(hi) : "l"(v));
    return make_float2(__uint_as_float(lo), __uint_as_float(hi));
}
__device__ __forceinline__ float ex2f(float x){ float r; asm("ex2.approx.f32 %0, %1;" : "=f"(r) : "f"(x)); return r; }

// ================= K1: per-node embeddings h -> g, a_s, a_d =================
// 1024 blocks x 128 threads; 8 nodes/block; thread = (node n = t&7, k-pair p = t>>3).
// Two-phase: h built cooperatively in smem (no redundant recompute); padded
// strides (33) make every LDS conflict-free. Head sums via shfl_xor(8,16).
__global__ void __launch_bounds__(128) k1_embed(
    const float* __restrict__ x, const float* __restrict__ Wp, const float* __restrict__ bp,
    const float* __restrict__ Wg, const float* __restrict__ att_src, const float* __restrict__ att_dst)
{
    __shared__ float xs[8*12];
    __shared__ float Wp_s[HIDN*DD];
    __shared__ float bp_s[HIDN];
    __shared__ float Wg_s[HIDN*33];     // padded rows: bank-conflict-free
    __shared__ float asr_s[HIDN], adr_s[HIDN];
    __shared__ float hs[8*33];          // padded rows

    int t  = threadIdx.x;
    int nb = blockIdx.x * 8;

    if (t < 8*12) xs[t] = x[(size_t)nb*12 + t];
    for (int i = t; i < HIDN*DD; i += 128) Wp_s[i] = Wp[i];
    for (int i = t; i < HIDN*HIDN; i += 128) {
        int k = i >> 5, d = i & 31;
        Wg_s[k*33 + d] = Wg[i];          // coalesced read, padded store
    }
    if (t < HIDN) { bp_s[t] = bp[t]; asr_s[t] = att_src[t]; adr_s[t] = att_dst[t]; }
    __syncthreads();

    int n = t & 7, p = t >> 3;           // p = k-pair index (0..15)
    int k0 = 2*p, k1 = 2*p + 1;

    // phase 1: h[n][k0], h[n][k1]
    {
        float a0 = bp_s[k0], a1 = bp_s[k1];
#pragma unroll
        for (int d = 0; d < DD; ++d) {
            float xv = xs[n*DD + d];
            a0 = fmaf(xv, Wp_s[k0*DD + d], a0);
            a1 = fmaf(xv, Wp_s[k1*DD + d], a1);
        }
        hs[n*33 + k0] = fmaxf(a0, 0.f);
        hs[n*33 + k1] = fmaxf(a1, 0.f);
    }
    __syncthreads();

    // phase 2: g[n][k0], g[n][k1] + head attention sums
    float acc0 = 0.f, acc1 = 0.f;
#pragma unroll
    for (int d = 0; d < HIDN; ++d) {
        float hd = hs[n*33 + d];
        acc0 = fmaf(hd, Wg_s[k0*33 + d], acc0);
        acc1 = fmaf(hd, Wg_s[k1*33 + d], acc1);
    }
    int node = nb + n;
    *(float2*)(g_buf + (size_t)node*HIDN + k0) = make_float2(acc0, acc1);

    float asum  = acc0*asr_s[k0] + acc1*asr_s[k1];
    float adsum = acc0*adr_s[k0] + acc1*adr_s[k1];
    // reduce over the 4 k-pairs of each head (partners t^8, t^16: same n)
    asum  += __shfl_xor_sync(0xffffffffu, asum, 8);
    asum  += __shfl_xor_sync(0xffffffffu, asum, 16);
    adsum += __shfl_xor_sync(0xffffffffu, adsum, 8);
    adsum += __shfl_xor_sync(0xffffffffu, adsum, 16);
    if ((p & 3) == 0) {
        as_buf[node*NHEAD + (p >> 2)] = asum;
        ad_buf[node*NHEAD + (p >> 2)] = adsum;
    }
}

// ================= K2: attention softmax + h_gnn + ti/tjT + pi/pj =================
// Grid (32 j-tiles x 16 b), 256 threads, static smem ~39.4KB.
// Warp w = private 64-i segment; covers 16 j (2 j-groups per lane).
__global__ void __launch_bounds__(256) k2_attn(
    const int* __restrict__ adj, const float* __restrict__ bias_g,
    const float* __restrict__ W1, const float* __restrict__ b1,
    const float* __restrict__ w2)
{
    __shared__ float    part_s[8*16*4*9];      // seg, j, h, (den + 8 num)
    __shared__ float    asT_s[4*520];          // a_s transposed
    __shared__ unsigned mask_s[NNODE];         // (adj|eye) 16-bit column masks
    __shared__ float    hg_s[16*33];
    __shared__ float    w2_s[HIDN];
    __shared__ float    W1T_s[32*65];          // W1T[d][o], pad 65

    int t  = threadIdx.x;
    int b  = blockIdx.y;
    int j0 = blockIdx.x * 16;
    int w = t >> 5, lane = t & 31;

    const float* asp = as_buf + (size_t)b * NNODE * NHEAD;
    for (int idx = t; idx < NNODE*NHEAD; idx += 256) {
        int i = idx >> 2, h = idx & 3;
        asT_s[h*520 + i] = asp[idx];
    }
    if (t < HIDN) w2_s[t] = w2[t];

    for (int idx = t; idx < 32*64; idx += 256) {
        int r = idx >> 6, c = idx & 63;     // W1[r][c], coalesced
        int d = (c < 32) ? c : (c - 32);
        int o = (c < 32) ? r : (r + 32);
        W1T_s[d*65 + o] = W1[idx];
    }

    // mask: warp w builds its own i-segment [64w, 64w+64); 2 rows per ballot.
    {
        int jl = lane & 15, ip = lane >> 4;   // lanes 0-15: row i, 16-31: row i+1
        const int* ab = adj + (size_t)b * NNODE * NNODE + j0 + jl;
        int base = w * 64;
#pragma unroll
        for (int c = 0; c < 8; ++c) {
            int i = base + c*8;
            int a0 = ab[(size_t)(i+0+ip) * NNODE];
            int a1 = ab[(size_t)(i+2+ip) * NNODE];
            int a2 = ab[(size_t)(i+4+ip) * NNODE];
            int a3 = ab[(size_t)(i+6+ip) * NNODE];
            unsigned m0 = __ballot_sync(0xffffffffu, (a0 != 0) || (i+0+ip == j0 + jl));
            unsigned m1 = __ballot_sync(0xffffffffu, (a1 != 0) || (i+2+ip == j0 + jl));
            unsigned m2 = __ballot_sync(0xffffffffu, (a2 != 0) || (i+4+ip == j0 + jl));
            unsigned m3 = __ballot_sync(0xffffffffu, (a3 != 0) || (i+6+ip == j0 + jl));
            if (lane == 0) {
                mask_s[i+0] = m0 & 0xFFFFu; mask_s[i+1] = m0 >> 16;
                mask_s[i+2] = m1 & 0xFFFFu; mask_s[i+3] = m1 >> 16;
                mask_s[i+4] = m2 & 0xFFFFu; mask_s[i+5] = m2 >> 16;
                mask_s[i+6] = m3 & 0xFFFFu; mask_s[i+7] = m3 >> 16;
            }
        }
    }
    __syncthreads();

    int h = lane & 3, jslot = lane >> 2;   // jslot 0..7

    float adv[2];
#pragma unroll
    for (int g = 0; g < 2; ++g)
        adv[g] = ad_buf[((size_t)(b*NNODE) + j0 + g*8 + jslot)*NHEAD + h];
    unsigned bit0 = 1u << jslot;

    float den[2] = {0,0};
    ull num[8];
#pragma unroll
    for (int q = 0; q < 8; ++q) num[q] = 0ull;

    const ulonglong2* gq2 = (const ulonglong2*)(g_buf + (size_t)b * NNODE * HIDN);

    const float C06 = 0.8656170246f;   // 0.6 * log2(e)
    const float C04 = 0.5770780164f;   // 0.4 * log2(e)

    int ibeg = w * 64, iend = ibeg + 64;
#pragma unroll 2
    for (int i = ibeg; i < iend; ++i) {
        float asv   = asT_s[h*520 + i];
        unsigned mw = mask_s[i];
        ulonglong2 ga = gq2[i*8 + h*2];       // LDG.128, one L2 line per warp-i
        ulonglong2 gb = gq2[i*8 + h*2 + 1];
#pragma unroll
        for (int g = 0; g < 2; ++g) {
            float s = asv + adv[g];
            float arg = fmaf(C04, fabsf(s), C06*s);  // log2e * leakyrelu(s, 0.2)
            float e = ex2f(arg);
            e = (mw & (bit0 << (8*g))) ? e : 0.f;
            den[g] += e;
            ull e2 = pack2(e, e);
            num[4*g+0] = fma2(e2, ga.x, num[4*g+0]);
            num[4*g+1] = fma2(e2, ga.y, num[4*g+1]);
            num[4*g+2] = fma2(e2, gb.x, num[4*g+2]);
            num[4*g+3] = fma2(e2, gb.y, num[4*g+3]);
        }
    }
#pragma unroll
    for (int g = 0; g < 2; ++g) {
        float* pp = part_s + ((w*16 + g*8 + jslot)*4 + h)*9;
        pp[0] = den[g];
#pragma unroll
        for (int c = 0; c < 4; ++c) {
            float2 f = unpack2(num[4*g+c]); pp[1+2*c] = f.x; pp[2+2*c] = f.y;
        }
    }
    __syncthreads();

    // reduce 8 i-segments -> h_gnn[j][32] (+bias_g)
    if (t < 64) {
        int jl = t >> 2, hh = t & 3;
        float dn = 0.f, nm[8] = {0,0,0,0,0,0,0,0};
#pragma unroll
        for (int q = 0; q < 8; ++q) {
            const float* pp = part_s + ((q*16 + jl)*4 + hh)*9;
            dn += pp[0];
#pragma unroll
            for (int c = 0; c < 8; ++c) nm[c] += pp[1+c];
        }
        float inv = __fdividef(1.f, dn);    // diag always unmasked => dn > 0
#pragma unroll
        for (int c = 0; c < 8; ++c)
            hg_s[jl*33 + hh*8 + c] = fmaf(nm[c], inv, bias_g[hh*8 + c]);
    }
    __syncthreads();

    // ti' = h_gnn@W1[:,:32]^T + b1 ; tj = h_gnn@W1[:,32:]^T (transposed layout);
    // pi/pj via warp reduction (warp-uniform j & half).
    for (int k = t; k < 16*64; k += 256) {
        int j = k >> 6, o = k & 63;
        float acc = (o < 32) ? b1[o] : 0.f;
#pragma unroll
        for (int d = 0; d < 32; ++d) acc = fmaf(hg_s[j*33 + d], W1T_s[d*65 + o], acc);
        size_t node = (size_t)(b*NNODE) + j0 + j;
        if (o < 32) {
            ti_buf[node*32 + o] = acc;
        } else {
            int oo = o - 32;
            tjT_buf[(((size_t)b*16 + (oo>>1))*NNODE + j0 + j)*2 + (oo & 1)] = acc;
        }
        float v = acc * w2_s[o & 31];
        v += __shfl_xor_sync(0xffffffffu, v, 16);
        v += __shfl_xor_sync(0xffffffffu, v, 8);
        v += __shfl_xor_sync(0xffffffffu, v, 4);
        v += __shfl_xor_sync(0xffffffffu, v, 2);
        v += __shfl_xor_sync(0xffffffffu, v, 1);
        if (lane == 0) {
            if (o < 32) pi_buf[node] = 0.5f * v;
            else        pj_buf[node] = 0.5f * v;
        }
    }
}

// ================= K4: pairwise edge scorer =================
// sum_h w2*relu(ti+tj) = pi + pj + sum_h (w2/2)*|ti+tj| ; |.| = packed AND.
// Dual i-chains; K4_IT=32 -> grid 512 (finer wave granularity / smaller tail).
#define K4_IT 32
__global__ void __launch_bounds__(256, 2) k4_score(
    const int* __restrict__ adj, const float* __restrict__ w2,
    const float* __restrict__ b2, float* __restrict__ out)
{
    __shared__ ull   ti_s[K4_IT*16];
    __shared__ float pi_s[K4_IT];
    __shared__ ull   w2p_s[16];
    int t = threadIdx.x, lane = t & 31, w = t >> 5;
    int b  = blockIdx.z;
    int i0 = blockIdx.y * K4_IT;
    int j  = blockIdx.x * 256 + w*32 + lane;

    const ull* tiu = (const ull*)ti_buf + ((size_t)(b*NNODE) + i0)*16;
    for (int idx = t; idx < K4_IT*16; idx += 256) ti_s[idx] = tiu[idx];
    if (t < K4_IT) pi_s[t] = pi_buf[(size_t)(b*NNODE) + i0 + t];
    if (t < 16)    w2p_s[t] = pack2(0.5f*w2[2*t], 0.5f*w2[2*t+1]);
    __syncthreads();

    ull tj2[16], w2r[16];
    const ull* tjp = (const ull*)tjT_buf;
#pragma unroll
    for (int p = 0; p < 16; ++p) tj2[p] = tjp[((size_t)b*16 + p)*NNODE + j];
#pragma unroll
    for (int p = 0; p < 16; ++p) w2r[p] = w2p_s[p];
    float pj  = pj_buf[(size_t)(b*NNODE) + j];
    float b2v = b2[0] + pj;

    const int* arow = adj + ((size_t)(b*NNODE) + i0)*NNODE + j;
    float*     orow = out + ((size_t)(b*NNODE) + i0)*NNODE + j;
    const ull ABS2 = 0x7FFFFFFF7FFFFFFFull;

    for (int ib = 0; ib < K4_IT; ib += 4) {
        int av[4];
#pragma unroll
        for (int k = 0; k < 4; ++k) av[k] = arow[(size_t)(ib + k) * NNODE];

#pragma unroll
        for (int kk = 0; kk < 2; ++kk) {
            int iA = ib + kk*2, iB = iA + 1;
            const ulonglong2* tpA = (const ulonglong2*)&ti_s[iA*16];
            const ulonglong2* tpB = (const ulonglong2*)&ti_s[iB*16];
            ull aA0 = 0, aA1 = 0, aB0 = 0, aB1 = 0;
#pragma unroll
            for (int q = 0; q < 8; ++q) {
                ulonglong2 tvA = tpA[q];                  // LDS.128 broadcast (chain A)
                ulonglong2 tvB = tpB[q];                  // LDS.128 broadcast (chain B)
                ull sA0 = add2(tj2[2*q],   tvA.x) & ABS2; // packed |ti+tj|
                ull sB0 = add2(tj2[2*q],   tvB.x) & ABS2;
                ull sA1 = add2(tj2[2*q+1], tvA.y) & ABS2;
                ull sB1 = add2(tj2[2*q+1], tvB.y) & ABS2;
                aA0 = fma2(w2r[2*q],   sA0, aA0);
                aB0 = fma2(w2r[2*q],   sB0, aB0);
                aA1 = fma2(w2r[2*q+1], sA1, aA1);
                aB1 = fma2(w2r[2*q+1], sB1, aB1);
            }
            float2 sfA = unpack2(add2(aA0, aA1));
            float2 sfB = unpack2(add2(aB0, aB1));
            float logitA = sfA.x + sfA.y + pi_s[iA] + b2v;
            float logitB = sfB.x + sfB.y + pi_s[iB] + b2v;
            float eA  = ex2f(-1.4426950409f * logitA);    // exp(-logit)
            float eB  = ex2f(-1.4426950409f * logitB);
            float scA = __fdividef(1.f, 1.f + eA);
            float scB = __fdividef(1.f, 1.f + eB);

            orow[(size_t)iA * NNODE] = (av[kk*2]   != 0 && (i0 + iA) != j) ? scA : 0.f;
            orow[(size_t)iB * NNODE] = (av[kk*2+1] != 0 && (i0 + iB) != j) ? scB : 0.f;
        }
    }
}

// ================= launch =================
extern "C" void kernel_launch(void* const* d_in, const int* in_sizes, int n_in,
                              void* d_out, int out_size)
{
    const float* x        = (const float*)d_in[0];
    const int*   adj      = (const int*)  d_in[1];
    const float* Wp       = (const float*)d_in[2];
    const float* bp       = (const float*)d_in[3];
    const float* Wg       = (const float*)d_in[4];
    const float* att_src  = (const float*)d_in[5];
    const float* att_dst  = (const float*)d_in[6];
    const float* bias_g   = (const float*)d_in[7];
    const float* W1       = (const float*)d_in[8];
    const float* b1       = (const float*)d_in[9];
    const float* w2       = (const float*)d_in[10];
    const float* b2       = (const float*)d_in[11];
    float* out = (float*)d_out;

    k1_embed<<<BB*NNODE/8, 128>>>(x, Wp, bp, Wg, att_src, att_dst);

    k2_attn<<<dim3(NNODE/16, BB), 256>>>(adj, bias_g, W1, b1, w2);

    k4_score<<<dim3(2, NNODE/K4_IT, BB), 256>>>(adj, w2, b2, out);
}